// round 15
// baseline (speedup 1.0000x reference)
#include <cuda_runtime.h>

#define NNODES 50000
#define NEDGES 320000
#define OUT_V_OFF 3200000
#define SC_S_OFF  12800000
#define SC_V_OFF  16000000

typedef unsigned long long u64;

// ---- scratch (__device__ globals: allocation-free) ----
__device__ float g_s_scr[NNODES * 64];
__device__ float g_v_scr[NNODES * 192];   // [n][x][c]
__device__ float g_ms[NNODES * 128];      // [n][2C]
__device__ float g_mv[NNODES * 576];      // [n][3C][3]  (x innermost)
// pre-duplicated node weight panels: 22 panels x 64x64 u64 (w,w)
__device__ __align__(16) u64 g_wnd[22 * 4096];

__device__ __forceinline__ float silu_f(float x) { return x / (1.0f + __expf(-x)); }

// ---- packed fp32x2 primitives ----
__device__ __forceinline__ u64 pack2(float lo, float hi) {
    u64 r; asm("mov.b64 %0, {%1, %2};" : "=l"(r) : "f"(lo), "f"(hi)); return r;
}
__device__ __forceinline__ u64 fma2(u64 a, u64 b, u64 c) {
    u64 d; asm("fma.rn.f32x2 %0, %1, %2, %3;" : "=l"(d) : "l"(a), "l"(b), "l"(c)); return d;
}
__device__ __forceinline__ void unpack2(u64 v, float& lo, float& hi) {
    asm("mov.b64 {%0, %1}, %2;" : "=f"(lo), "=f"(hi) : "l"(v));
}

__device__ __forceinline__ void red4v(float* p, float4 v) {
    asm volatile("red.global.add.v4.f32 [%0], {%1, %2, %3, %4};"
                 :: "l"(p), "f"(v.x), "f"(v.y), "f"(v.z), "f"(v.w) : "memory");
}

// ---- cp.async helpers ----
__device__ __forceinline__ unsigned smaddr(const void* p) {
    return (unsigned)__cvta_generic_to_shared(p);
}
__device__ __forceinline__ void cp16(unsigned dst, const void* src) {
    asm volatile("cp.async.cg.shared.global [%0], [%1], 16;" :: "r"(dst), "l"(src) : "memory");
}
__device__ __forceinline__ void cp_commit() {
    asm volatile("cp.async.commit_group;" ::: "memory");
}

__device__ __forceinline__ float4 f4mul(float4 a, float4 b) {
    return make_float4(a.x*b.x, a.y*b.y, a.z*b.z, a.w*b.w);
}
__device__ __forceinline__ float4 f4muls(float4 a, float s) {
    return make_float4(a.x*s, a.y*s, a.z*s, a.w*s);
}
__device__ __forceinline__ float4 f4sub(float4 a, float4 b) {
    return make_float4(a.x-b.x, a.y-b.y, a.z-b.z, a.w-b.w);
}
__device__ __forceinline__ float4 f4add(float4 a, float4 b) {
    return make_float4(a.x+b.x, a.y+b.y, a.z+b.z, a.w+b.w);
}

__device__ __forceinline__ void scatter_vec_group(float* dst, float4 val,
                                                  float4 ax, float4 ay, float4 az) {
    red4v(dst + 0, make_float4(val.x*ax.x, val.x*ay.x, val.x*az.x, val.y*ax.y));
    red4v(dst + 4, make_float4(val.y*ay.y, val.y*az.y, val.z*ax.z, val.z*ay.z));
    red4v(dst + 8, make_float4(val.z*az.z, val.w*ax.w, val.w*ay.w, val.w*az.w));
}

// 8x2 register-tile GEMM, float2 weights (edge/out kernels).
template <int K, int LDA>
__device__ __forceinline__ void gemm8x2(const float* __restrict__ A,
                                        const float* __restrict__ W,
                                        u64 Y[4][2]) {
#pragma unroll
    for (int rp = 0; rp < 4; rp++) { Y[rp][0] = 0ull; Y[rp][1] = 0ull; }
#pragma unroll 8
    for (int c = 0; c < K; c++) {
        ulonglong2 a01 = *(const ulonglong2*)(A + c * LDA);
        ulonglong2 a23 = *(const ulonglong2*)(A + c * LDA + 4);
        float2 w = *(const float2*)(W + c * 64);
        u64 w0 = pack2(w.x, w.x), w1 = pack2(w.y, w.y);
        Y[0][0] = fma2(a01.x, w0, Y[0][0]);
        Y[0][1] = fma2(a01.x, w1, Y[0][1]);
        Y[1][0] = fma2(a01.y, w0, Y[1][0]);
        Y[1][1] = fma2(a01.y, w1, Y[1][1]);
        Y[2][0] = fma2(a23.x, w0, Y[2][0]);
        Y[2][1] = fma2(a23.x, w1, Y[2][1]);
        Y[3][0] = fma2(a23.y, w0, Y[3][0]);
        Y[3][1] = fma2(a23.y, w1, Y[3][1]);
    }
}

// 8x2 register-tile GEMM with PRE-DUPLICATED u64 weights (node kernel).
// k-step: 3x LDS.128 + 8x FFMA2 = 11 issues, zero MOVs.
template <int K, int LDA>
__device__ __forceinline__ void gemm8x2d(const float* __restrict__ A,
                                         const u64* __restrict__ Wd,
                                         u64 Y[4][2]) {
#pragma unroll
    for (int rp = 0; rp < 4; rp++) { Y[rp][0] = 0ull; Y[rp][1] = 0ull; }
#pragma unroll 8
    for (int c = 0; c < K; c++) {
        ulonglong2 a01 = *(const ulonglong2*)(A + c * LDA);
        ulonglong2 a23 = *(const ulonglong2*)(A + c * LDA + 4);
        ulonglong2 w = *(const ulonglong2*)(Wd + c * 64);
        Y[0][0] = fma2(a01.x, w.x, Y[0][0]);
        Y[0][1] = fma2(a01.x, w.y, Y[0][1]);
        Y[1][0] = fma2(a01.y, w.x, Y[1][0]);
        Y[1][1] = fma2(a01.y, w.y, Y[1][1]);
        Y[2][0] = fma2(a23.x, w.x, Y[2][0]);
        Y[2][1] = fma2(a23.x, w.y, Y[2][1]);
        Y[3][0] = fma2(a23.y, w.x, Y[3][0]);
        Y[3][1] = fma2(a23.y, w.y, Y[3][1]);
    }
}

// ===================== K0: zero scratch =====================
__global__ void zero_kernel() {
    long i = (long)blockIdx.x * blockDim.x + threadIdx.x;
    long t = (long)gridDim.x * blockDim.x;
    float4 z = make_float4(0.f, 0.f, 0.f, 0.f);
    for (long j = i; j < (long)NNODES * 128 / 4; j += t) ((float4*)g_ms)[j] = z;
    for (long j = i; j < (long)NNODES * 576 / 4; j += t) ((float4*)g_mv)[j] = z;
}

// ===================== Kp: node weight duplication prep =====================
// panel p<10: Wscs attr p; p in 10..19: Wscv attr p-10; 20: Wses; 21: Wsev
__global__ void prep_kernel(const float* __restrict__ Wscs,
                            const float* __restrict__ Wscv,
                            const float* __restrict__ Wses,
                            const float* __restrict__ Wsev) {
    int idx = blockIdx.x * blockDim.x + threadIdx.x;
    if (idx >= 22 * 4096) return;
    int p = idx >> 12, rem = idx & 4095;
    int c = rem >> 6, d = rem & 63;
    float v;
    if (p < 10)      v = Wscs[(c * 10 + p) * 64 + d];
    else if (p < 20) v = Wscv[(c * 10 + (p - 10)) * 64 + d];
    else if (p == 20) v = Wses[c * 64 + d];
    else              v = Wsev[c * 64 + d];
    g_wnd[idx] = pack2(v, v);
}

// ===================== K1: node side — duplicated-weight panels ====
// 512 threads, grid 391. smem (floats):
//   fsm @0     : [64][132] = 8448
//   fvm @8448  : 3 x [64][132] = 25344
//   WB0 @33792 : 8192 (u64[64][64] panel buf 0)
//   WB1 @41984 : 8192 (panel buf 1)
//   atm @50176 : [128][10] = 1280
// total 51456 floats = 205.8 KB -> 1 CTA/SM, 16 warps
#define NLDA 132
#define NFSM 0
#define NFVM 8448
#define NWB0 33792
#define NWB1 41984
#define NATM 50176
#define K1_SMEM_BYTES (51456 * 4)
#define NTILE 128

// stage one duplicated 64x64 panel (32KB) via cp.async; one commit group.
__device__ __forceinline__ void stage_panel_dup(u64* dst, const u64* src, int tid) {
#pragma unroll
    for (int i = tid; i < 2048; i += 512)
        cp16(smaddr(dst + i * 2), src + i * 2);
    cp_commit();
}

__global__ void __launch_bounds__(512, 1) node_kernel(
    const float* __restrict__ attrs_g, const float* __restrict__ fs_g,
    const float* __restrict__ fv_g, float* __restrict__ out) {
    extern __shared__ float sm[];
    const int tid = threadIdx.x;
    const int n0 = blockIdx.x * NTILE;
    const int tx = tid & 31, ty = tid >> 5;
    const int nb = ty * 8, db = tx * 2;   // db in u64 units for weights

    stage_panel_dup((u64*)(sm + NWB0), g_wnd + 0 * 4096, tid);
    stage_panel_dup((u64*)(sm + NWB1), g_wnd + 1 * 4096, tid);

    for (int idx = tid; idx < NTILE * 64; idx += 512) {
        int n = idx >> 6, c = idx & 63, gn = n0 + n;
        sm[NFSM + c * NLDA + n] = (gn < NNODES) ? fs_g[gn * 64 + c] : 0.0f;
    }
    for (int idx = tid; idx < NTILE * 192; idx += 512) {
        int n = idx / 192, r = idx - n * 192, c = r / 3, x = r - c * 3, gn = n0 + n;
        sm[NFVM + x * 8448 + c * NLDA + n] = (gn < NNODES) ? fv_g[gn * 192 + r] : 0.0f;
    }
    for (int idx = tid; idx < NTILE * 10; idx += 512) {
        int n = idx / 10, gn = n0 + n;
        sm[NATM + idx] = (gn < NNODES) ? attrs_g[gn * 10 + (idx - n * 10)] : 0.0f;
    }

    u64 acc_s[4][2], acc_v[3][4][2], Y[4][2];
#pragma unroll
    for (int rp = 0; rp < 4; rp++) { acc_s[rp][0] = 0ull; acc_s[rp][1] = 0ull; }
#pragma unroll
    for (int x = 0; x < 3; x++)
#pragma unroll
        for (int rp = 0; rp < 4; rp++) { acc_v[x][rp][0] = 0ull; acc_v[x][rp][1] = 0ull; }

    const float isc = rsqrtf(640.0f);

#pragma unroll 1
    for (int p = 0; p < 22; p++) {
        if (p == 21) asm volatile("cp.async.wait_group 0;" ::: "memory");
        else         asm volatile("cp.async.wait_group 1;" ::: "memory");
        __syncthreads();
        const u64* WB = (const u64*)(sm + ((p & 1) ? NWB1 : NWB0)) + db;

        if (p < 10) {
            gemm8x2d<64, NLDA>(sm + NFSM + nb, WB, Y);
#pragma unroll
            for (int rp = 0; rp < 4; rp++) {
                u64 av2 = pack2(sm[NATM + (nb + 2*rp) * 10 + p],
                                sm[NATM + (nb + 2*rp + 1) * 10 + p]);
                acc_s[rp][0] = fma2(av2, Y[rp][0], acc_s[rp][0]);
                acc_s[rp][1] = fma2(av2, Y[rp][1], acc_s[rp][1]);
            }
        } else if (p < 20) {
            const int a = p - 10;
#pragma unroll 1
            for (int x = 0; x < 3; x++) {
                gemm8x2d<64, NLDA>(sm + NFVM + x * 8448 + nb, WB, Y);
#pragma unroll
                for (int rp = 0; rp < 4; rp++) {
                    u64 av2 = pack2(sm[NATM + (nb + 2*rp) * 10 + a],
                                    sm[NATM + (nb + 2*rp + 1) * 10 + a]);
                    acc_v[x][rp][0] = fma2(av2, Y[rp][0], acc_v[x][rp][0]);
                    acc_v[x][rp][1] = fma2(av2, Y[rp][1], acc_v[x][rp][1]);
                }
            }
        } else if (p == 20) {
            gemm8x2d<64, NLDA>(sm + NFSM + nb, WB, Y);
#pragma unroll
            for (int rp = 0; rp < 4; rp++) {
                float y0l, y0h, y1l, y1h;
                unpack2(Y[rp][0], y0l, y0h);
                unpack2(Y[rp][1], y1l, y1h);
                int gn0 = n0 + nb + 2*rp;
                if (gn0 < NNODES)
                    *(float2*)(g_s_scr + gn0 * 64 + db) = make_float2(y0l*0.125f, y1l*0.125f);
                if (gn0 + 1 < NNODES)
                    *(float2*)(g_s_scr + (gn0+1) * 64 + db) = make_float2(y0h*0.125f, y1h*0.125f);
            }
        } else {
#pragma unroll 1
            for (int x = 0; x < 3; x++) {
                gemm8x2d<64, NLDA>(sm + NFVM + x * 8448 + nb, WB, Y);
#pragma unroll
                for (int rp = 0; rp < 4; rp++) {
                    float y0l, y0h, y1l, y1h;
                    unpack2(Y[rp][0], y0l, y0h);
                    unpack2(Y[rp][1], y1l, y1h);
                    int gn0 = n0 + nb + 2*rp;
                    if (gn0 < NNODES)
                        *(float2*)(g_v_scr + gn0 * 192 + x * 64 + db) =
                            make_float2(y0l*0.125f, y1l*0.125f);
                    if (gn0 + 1 < NNODES)
                        *(float2*)(g_v_scr + (gn0+1) * 192 + x * 64 + db) =
                            make_float2(y0h*0.125f, y1h*0.125f);
                }
            }
        }
        __syncthreads();
        if (p + 2 < 22)
            stage_panel_dup((u64*)(sm + ((p & 1) ? NWB1 : NWB0)),
                            g_wnd + (p + 2) * 4096, tid);
    }

    // ---- skip-connection outputs ----
#pragma unroll
    for (int rp = 0; rp < 4; rp++) {
        float s0l, s0h, s1l, s1h;
        unpack2(acc_s[rp][0], s0l, s0h);
        unpack2(acc_s[rp][1], s1l, s1h);
        float v0l[3], v0h[3], v1l[3], v1h[3];
#pragma unroll
        for (int x = 0; x < 3; x++) {
            unpack2(acc_v[x][rp][0], v0l[x], v0h[x]);
            unpack2(acc_v[x][rp][1], v1l[x], v1h[x]);
        }
        int gn0 = n0 + nb + 2*rp;
        if (gn0 < NNODES) {
            *(float2*)(out + SC_S_OFF + gn0 * 64 + db) = make_float2(s0l*isc, s1l*isc);
#pragma unroll
            for (int x = 0; x < 3; x++) {
                out[SC_V_OFF + (gn0 * 64 + db) * 3 + x]     = v0l[x] * isc;
                out[SC_V_OFF + (gn0 * 64 + db + 1) * 3 + x] = v1l[x] * isc;
            }
        }
        if (gn0 + 1 < NNODES) {
            *(float2*)(out + SC_S_OFF + (gn0+1) * 64 + db) = make_float2(s0h*isc, s1h*isc);
#pragma unroll
            for (int x = 0; x < 3; x++) {
                out[SC_V_OFF + ((gn0+1) * 64 + db) * 3 + x]     = v0h[x] * isc;
                out[SC_V_OFF + ((gn0+1) * 64 + db + 1) * 3 + x] = v1h[x] * isc;
            }
        }
    }
}

// ===================== K2: edge side — R13 version (2 CTAs/SM) ========
#define SA 0
#define SB 8960
#define SW1 17920
#define WS0 18432
#define WS1 22528
#define SMETA 26624
#define K2_SMEM_BYTES (27392 * 4)

__device__ __forceinline__ void store_actT(float* dst, const u64 Y[4][2],
                                           int nb, int db, float scale) {
#pragma unroll
    for (int c = 0; c < 2; c++) {
        float y0l, y0h, y1l, y1h, y2l, y2h, y3l, y3h;
        unpack2(Y[0][c], y0l, y0h);
        unpack2(Y[1][c], y1l, y1h);
        unpack2(Y[2][c], y2l, y2h);
        unpack2(Y[3][c], y3l, y3h);
        float* base = dst + (db + c) * 140 + nb;
        *(float4*)(base)     = make_float4(silu_f(y0l*scale), silu_f(y0h*scale),
                                           silu_f(y1l*scale), silu_f(y1h*scale));
        *(float4*)(base + 4) = make_float4(silu_f(y2l*scale), silu_f(y2h*scale),
                                           silu_f(y3l*scale), silu_f(y3h*scale));
    }
}

__device__ __forceinline__ void stage_w64(float* dst, const float* src,
                                          int ld_src, int col0, int tid) {
#pragma unroll
    for (int i = tid; i < 1024; i += 512) {
        int k = i >> 4, c4 = (i & 15) * 4;
        cp16(smaddr(dst + k * 64 + c4), src + k * ld_src + col0 + c4);
    }
    cp_commit();
}

__global__ void __launch_bounds__(512, 2) edge_kernel(
    const float* __restrict__ ef_g, const float* __restrict__ sh0_g,
    const float* __restrict__ sh1_g, const int* __restrict__ snd_g,
    const int* __restrict__ rcv_g,
    const float* __restrict__ W1, const float* __restrict__ W2,
    const float* __restrict__ W3, const float* __restrict__ W4) {
    extern __shared__ float sm[];
    const int tid = threadIdx.x;
    const int e0 = blockIdx.x * 128;
    const int tx = tid & 31, ty = tid >> 5;
    const int nb = ty * 8, db = tx * 2;
    const int e_loc = tid >> 2, cg = tid & 3, ch = cg * 16;
    const float i3 = rsqrtf(3.0f), i2 = rsqrtf(2.0f), is8 = rsqrtf(8.0f);
    u64 Y[4][2];

    if (tid < 128) {
        int ge = e0 + tid;
        ((int*)(sm + SMETA))[tid]       = snd_g[ge];
        ((int*)(sm + SMETA + 128))[tid] = rcv_g[ge];
        sm[SMETA + 256 + tid] = sh0_g[ge];
        sm[SMETA + 384 + tid] = sh1_g[ge * 3 + 0];
        sm[SMETA + 512 + tid] = sh1_g[ge * 3 + 1];
        sm[SMETA + 640 + tid] = sh1_g[ge * 3 + 2];
    }
    for (int i = tid; i < 1024; i += 512) {
        int e = i >> 3, k = i & 7;
        sm[SA + k * 140 + e] = ef_g[e0 * 8 + i];
    }
    sm[SW1 + tid] = W1[tid];
    stage_w64(sm + WS0, W2, 64, 0, tid);
    stage_w64(sm + WS1, W3, 64, 0, tid);
    __syncthreads();

    gemm8x2<8, 140>(sm + SA + nb, sm + SW1 + db, Y);
    store_actT(sm + SB, Y, nb, db, is8);
    asm volatile("cp.async.wait_group 1;" ::: "memory");
    __syncthreads();

    gemm8x2<64, 140>(sm + SB + nb, sm + WS0 + db, Y);
    store_actT(sm + SA, Y, nb, db, 0.125f);
    asm volatile("cp.async.wait_group 0;" ::: "memory");
    __syncthreads();
    stage_w64(sm + WS0, W4, 320, 0 * 64, tid);

    gemm8x2<64, 140>(sm + SA + nb, sm + WS1 + db, Y);
    store_actT(sm + SB, Y, nb, db, 0.125f);
    __syncthreads();
    stage_w64(sm + WS1, W4, 320, 1 * 64, tid);

    const int s = ((const int*)(sm + SMETA))[e_loc];
    const int r = ((const int*)(sm + SMETA + 128))[e_loc];
    const float sh0v = sm[SMETA + 256 + e_loc];
    const float qx = sm[SMETA + 384 + e_loc];
    const float qy = sm[SMETA + 512 + e_loc];
    const float qz = sm[SMETA + 640 + e_loc];
    const float* sep = g_s_scr + s * 64 + ch;
    const float* vp  = g_v_scr + s * 192 + ch;

#pragma unroll 1
    for (int p = 0; p < 5; p++) {
        float* buf = sm + ((p & 1) ? WS1 : WS0);
        if (p < 4) asm volatile("cp.async.wait_group 1;" ::: "memory");
        else       asm volatile("cp.async.wait_group 0;" ::: "memory");
        __syncthreads();

        gemm8x2<64, 140>(sm + SB + nb, buf + db, Y);
#pragma unroll
        for (int rp = 0; rp < 4; rp++) {
            float y0l, y0h, y1l, y1h;
            unpack2(Y[rp][0], y0l, y0h);
            unpack2(Y[rp][1], y1l, y1h);
            int rrow = nb + 2*rp;
            *(float2*)(sm + SA + rrow * 68 + db)       = make_float2(y0l*0.125f, y1l*0.125f);
            *(float2*)(sm + SA + (rrow + 1) * 68 + db) = make_float2(y0h*0.125f, y1h*0.125f);
        }
        __syncthreads();
        if (p + 2 <= 4) stage_w64(buf, W4, 320, (p + 2) * 64, tid);

        const float* wrow = sm + SA + e_loc * 68 + ch;
        if (p == 0) {
            float* dst = g_ms + r * 128 + ch;
#pragma unroll
            for (int g = 0; g < 4; g++) {
                float4 wv = *(const float4*)(wrow + g*4);
                float4 se = *(const float4*)(sep + g*4);
                red4v(dst + g*4, f4muls(f4mul(wv, se), sh0v));
            }
        } else if (p == 1) {
            float* dst = g_ms + r * 128 + 64 + ch;
#pragma unroll
            for (int g = 0; g < 4; g++) {
                float4 wv = *(const float4*)(wrow + g*4);
                float4 vx = *(const float4*)(vp + g*4);
                float4 vy = *(const float4*)(vp + 64 + g*4);
                float4 vz = *(const float4*)(vp + 128 + g*4);
                float4 dt = f4add(f4add(f4muls(vx, qx), f4muls(vy, qy)), f4muls(vz, qz));
                red4v(dst + g*4, f4muls(f4mul(wv, dt), i3));
            }
        } else if (p == 2) {
            float* dst = g_mv + r * 576 + ch * 3;
            float4 aqx = make_float4(qx,qx,qx,qx);
            float4 aqy = make_float4(qy,qy,qy,qy);
            float4 aqz = make_float4(qz,qz,qz,qz);
#pragma unroll
            for (int g = 0; g < 4; g++) {
                float4 wv = *(const float4*)(wrow + g*4);
                float4 se = *(const float4*)(sep + g*4);
                scatter_vec_group(dst + g*12, f4mul(wv, se), aqx, aqy, aqz);
            }
        } else if (p == 3) {
            float* dst = g_mv + r * 576 + 192 + ch * 3;
#pragma unroll
            for (int g = 0; g < 4; g++) {
                float4 wv = *(const float4*)(wrow + g*4);
                float4 vx = *(const float4*)(vp + g*4);
                float4 vy = *(const float4*)(vp + 64 + g*4);
                float4 vz = *(const float4*)(vp + 128 + g*4);
                scatter_vec_group(dst + g*12, f4muls(wv, sh0v), vx, vy, vz);
            }
        } else {
            float* dst = g_mv + r * 576 + 384 + ch * 3;
#pragma unroll
            for (int g = 0; g < 4; g++) {
                float4 wv = *(const float4*)(wrow + g*4);
                float4 vx = *(const float4*)(vp + g*4);
                float4 vy = *(const float4*)(vp + 64 + g*4);
                float4 vz = *(const float4*)(vp + 128 + g*4);
                float4 crx = f4sub(f4muls(vy, qz), f4muls(vz, qy));
                float4 cry = f4sub(f4muls(vz, qx), f4muls(vx, qz));
                float4 crz = f4sub(f4muls(vx, qy), f4muls(vy, qx));
                scatter_vec_group(dst + g*12, f4muls(wv, i2), crx, cry, crz);
            }
        }
    }
}

// ===================== K3: output linear (R13 version) =====================
#define K3_SMEM_BYTES (25344 * 4)
__global__ void __launch_bounds__(256, 2) out_kernel(
    const float* __restrict__ Wouts, const float* __restrict__ Woutv,
    float* __restrict__ out) {
    extern __shared__ float sm[];
    float* msm = sm;
    float* wbuf = sm + 13056;
    const int tid = threadIdx.x;
    const int n0 = blockIdx.x * 64;
    const int tx = tid & 31, ty = tid >> 5;
    const int nb = ty * 8, db = tx * 2;
    u64 Y[4][2];

    for (int idx = tid; idx < 8192; idx += 256) {
        int n = idx >> 7, k = idx & 127, gn = n0 + n;
        msm[k * 68 + n] = (gn < NNODES) ? g_ms[gn * 128 + k] : 0.0f;
    }
    for (int idx = tid; idx < 8192; idx += 256) wbuf[idx] = Wouts[idx];
    __syncthreads();
    gemm8x2<128, 68>(msm + nb, wbuf + db, Y);
    const float ss = rsqrtf(128.0f) / 16.0f;
#pragma unroll
    for (int rp = 0; rp < 4; rp++) {
        float y0l, y0h, y1l, y1h;
        unpack2(Y[rp][0], y0l, y0h);
        unpack2(Y[rp][1], y1l, y1h);
        int gn0 = n0 + nb + 2*rp;
        if (gn0 < NNODES)
            *(float2*)(out + gn0 * 64 + db) = make_float2(y0l*ss, y1l*ss);
        if (gn0 + 1 < NNODES)
            *(float2*)(out + (gn0+1) * 64 + db) = make_float2(y0h*ss, y1h*ss);
    }
    __syncthreads();
    for (int idx = tid; idx < 12288; idx += 256) wbuf[idx] = Woutv[idx];
    const float sv = rsqrtf(192.0f) / 16.0f;
#pragma unroll 1
    for (int x = 0; x < 3; x++) {
        __syncthreads();
        for (int idx = tid; idx < 12288; idx += 256) {
            int n = idx / 192, k = idx - n * 192, gn = n0 + n;
            msm[k * 68 + n] = (gn < NNODES) ? g_mv[gn * 576 + k * 3 + x] : 0.0f;
        }
        __syncthreads();
        gemm8x2<192, 68>(msm + nb, wbuf + db, Y);
#pragma unroll
        for (int rp = 0; rp < 4; rp++) {
            float y0l, y0h, y1l, y1h;
            unpack2(Y[rp][0], y0l, y0h);
            unpack2(Y[rp][1], y1l, y1h);
            int gn0 = n0 + nb + 2*rp;
            if (gn0 < NNODES) {
                out[OUT_V_OFF + gn0 * 192 + db * 3 + x]       = y0l * sv;
                out[OUT_V_OFF + gn0 * 192 + (db + 1) * 3 + x] = y1l * sv;
            }
            if (gn0 + 1 < NNODES) {
                out[OUT_V_OFF + (gn0+1) * 192 + db * 3 + x]       = y0h * sv;
                out[OUT_V_OFF + (gn0+1) * 192 + (db + 1) * 3 + x] = y1h * sv;
            }
        }
    }
}

// ===================== launch =====================
extern "C" void kernel_launch(void* const* d_in, const int* in_sizes, int n_in,
                              void* d_out, int out_size) {
    const float* attrs = (const float*)d_in[0];
    const float* fs    = (const float*)d_in[1];
    const float* fv    = (const float*)d_in[2];
    const float* sh0   = (const float*)d_in[3];
    const float* sh1   = (const float*)d_in[4];
    const float* ef    = (const float*)d_in[5];
    const int*   snd   = (const int*)d_in[6];
    const int*   rcv   = (const int*)d_in[7];
    const float* Wscs  = (const float*)d_in[8];
    const float* Wscv  = (const float*)d_in[9];
    const float* Wses  = (const float*)d_in[10];
    const float* Wsev  = (const float*)d_in[11];
    const float* W1    = (const float*)d_in[12];
    const float* W2    = (const float*)d_in[13];
    const float* W3    = (const float*)d_in[14];
    const float* W4    = (const float*)d_in[15];
    const float* Wouts = (const float*)d_in[16];
    const float* Woutv = (const float*)d_in[17];
    float* out = (float*)d_out;

    cudaFuncSetAttribute(node_kernel, cudaFuncAttributeMaxDynamicSharedMemorySize, K1_SMEM_BYTES);
    cudaFuncSetAttribute(edge_kernel, cudaFuncAttributeMaxDynamicSharedMemorySize, K2_SMEM_BYTES);
    cudaFuncSetAttribute(out_kernel,  cudaFuncAttributeMaxDynamicSharedMemorySize, K3_SMEM_BYTES);

    zero_kernel<<<1024, 256>>>();
    prep_kernel<<<88, 1024>>>(Wscs, Wscv, Wses, Wsev);
    node_kernel<<<(NNODES + NTILE - 1) / NTILE, 512, K1_SMEM_BYTES>>>(
        attrs, fs, fv, out);
    edge_kernel<<<NEDGES / 128, 512, K2_SMEM_BYTES>>>(
        ef, sh0, sh1, snd, rcv, W1, W2, W3, W4);
    out_kernel<<<(NNODES + 63) / 64, 256, K3_SMEM_BYTES>>>(Wouts, Woutv, out);
}

// round 16
// speedup vs baseline: 1.1290x; 1.1290x over previous
#include <cuda_runtime.h>

#define NNODES 50000
#define NEDGES 320000
#define OUT_V_OFF 3200000
#define SC_S_OFF  12800000
#define SC_V_OFF  16000000

typedef unsigned long long u64;

// ---- scratch (__device__ globals: allocation-free) ----
__device__ float g_s_scr[NNODES * 64];
__device__ float g_v_scr[NNODES * 192];   // [n][x][c]
__device__ float g_ms[NNODES * 128];      // [n][2C]
__device__ float g_mv[NNODES * 576];      // [n][3C][3]  (x innermost)

__device__ __forceinline__ float silu_f(float x) { return x / (1.0f + __expf(-x)); }

// ---- packed fp32x2 primitives ----
__device__ __forceinline__ u64 pack2(float lo, float hi) {
    u64 r; asm("mov.b64 %0, {%1, %2};" : "=l"(r) : "f"(lo), "f"(hi)); return r;
}
__device__ __forceinline__ u64 fma2(u64 a, u64 b, u64 c) {
    u64 d; asm("fma.rn.f32x2 %0, %1, %2, %3;" : "=l"(d) : "l"(a), "l"(b), "l"(c)); return d;
}
__device__ __forceinline__ void unpack2(u64 v, float& lo, float& hi) {
    asm("mov.b64 {%0, %1}, %2;" : "=f"(lo), "=f"(hi) : "l"(v));
}

__device__ __forceinline__ void red4v(float* p, float4 v) {
    asm volatile("red.global.add.v4.f32 [%0], {%1, %2, %3, %4};"
                 :: "l"(p), "f"(v.x), "f"(v.y), "f"(v.z), "f"(v.w) : "memory");
}

// ---- cp.async helpers ----
__device__ __forceinline__ unsigned smaddr(const void* p) {
    return (unsigned)__cvta_generic_to_shared(p);
}
__device__ __forceinline__ void cp16(unsigned dst, const void* src) {
    asm volatile("cp.async.cg.shared.global [%0], [%1], 16;" :: "r"(dst), "l"(src) : "memory");
}
__device__ __forceinline__ void cp_commit() {
    asm volatile("cp.async.commit_group;" ::: "memory");
}

__device__ __forceinline__ float4 f4mul(float4 a, float4 b) {
    return make_float4(a.x*b.x, a.y*b.y, a.z*b.z, a.w*b.w);
}
__device__ __forceinline__ float4 f4muls(float4 a, float s) {
    return make_float4(a.x*s, a.y*s, a.z*s, a.w*s);
}
__device__ __forceinline__ float4 f4sub(float4 a, float4 b) {
    return make_float4(a.x-b.x, a.y-b.y, a.z-b.z, a.w-b.w);
}
__device__ __forceinline__ float4 f4add(float4 a, float4 b) {
    return make_float4(a.x+b.x, a.y+b.y, a.z+b.z, a.w+b.w);
}

// interleaved vector-path scatter: 12 contiguous floats [4ch x 3xyz] = 3 v4 reds.
__device__ __forceinline__ void scatter_vec_group(float* dst, float4 val,
                                                  float4 ax, float4 ay, float4 az) {
    red4v(dst + 0, make_float4(val.x*ax.x, val.x*ay.x, val.x*az.x, val.y*ax.y));
    red4v(dst + 4, make_float4(val.y*ay.y, val.y*az.y, val.z*ax.z, val.z*ay.z));
    red4v(dst + 8, make_float4(val.z*az.z, val.w*ax.w, val.w*ay.w, val.w*az.w));
}

// 8x2 register-tile GEMM using packed fp32x2.
template <int K, int LDA>
__device__ __forceinline__ void gemm8x2(const float* __restrict__ A,
                                        const float* __restrict__ W,
                                        u64 Y[4][2]) {
#pragma unroll
    for (int rp = 0; rp < 4; rp++) { Y[rp][0] = 0ull; Y[rp][1] = 0ull; }
#pragma unroll 8
    for (int c = 0; c < K; c++) {
        ulonglong2 a01 = *(const ulonglong2*)(A + c * LDA);
        ulonglong2 a23 = *(const ulonglong2*)(A + c * LDA + 4);
        float2 w = *(const float2*)(W + c * 64);
        u64 w0 = pack2(w.x, w.x), w1 = pack2(w.y, w.y);
        Y[0][0] = fma2(a01.x, w0, Y[0][0]);
        Y[0][1] = fma2(a01.x, w1, Y[0][1]);
        Y[1][0] = fma2(a01.y, w0, Y[1][0]);
        Y[1][1] = fma2(a01.y, w1, Y[1][1]);
        Y[2][0] = fma2(a23.x, w0, Y[2][0]);
        Y[2][1] = fma2(a23.x, w1, Y[2][1]);
        Y[3][0] = fma2(a23.y, w0, Y[3][0]);
        Y[3][1] = fma2(a23.y, w1, Y[3][1]);
    }
}

// ===================== K0: zero scratch =====================
__global__ void zero_kernel() {
    long i = (long)blockIdx.x * blockDim.x + threadIdx.x;
    long t = (long)gridDim.x * blockDim.x;
    float4 z = make_float4(0.f, 0.f, 0.f, 0.f);
    for (long j = i; j < (long)NNODES * 128 / 4; j += t) ((float4*)g_ms)[j] = z;
    for (long j = i; j < (long)NNODES * 576 / 4; j += t) ((float4*)g_mv)[j] = z;
}

// ===================== K1: node side — R13 version =====================
#define NLDA 132
#define NFSM 0
#define NFVM 8448
#define NWB0 33792
#define NWB1 37888
#define NATM 41984
#define K1_SMEM_BYTES (43264 * 4)
#define NTILE 128

__device__ __forceinline__ void stage_panel(float* dst, const float* src,
                                            int ld_src, int tid) {
#pragma unroll
    for (int i = tid; i < 1024; i += 512) {
        int k = i >> 4, c4 = (i & 15) * 4;
        cp16(smaddr(dst + k * 64 + c4), src + k * ld_src + c4);
    }
    cp_commit();
}

__global__ void __launch_bounds__(512, 1) node_kernel(
    const float* __restrict__ attrs_g, const float* __restrict__ fs_g,
    const float* __restrict__ fv_g,
    const float* __restrict__ Wscs, const float* __restrict__ Wscv,
    const float* __restrict__ Wses, const float* __restrict__ Wsev,
    float* __restrict__ out) {
    extern __shared__ float sm[];
    const int tid = threadIdx.x;
    const int n0 = blockIdx.x * NTILE;
    const int tx = tid & 31, ty = tid >> 5;
    const int nb = ty * 8, db = tx * 2;

    stage_panel(sm + NWB0, Wscs + 0 * 64, 640, tid);
    stage_panel(sm + NWB1, Wscs + 1 * 64, 640, tid);

    for (int idx = tid; idx < NTILE * 64; idx += 512) {
        int n = idx >> 6, c = idx & 63, gn = n0 + n;
        sm[NFSM + c * NLDA + n] = (gn < NNODES) ? fs_g[gn * 64 + c] : 0.0f;
    }
    for (int idx = tid; idx < NTILE * 192; idx += 512) {
        int n = idx / 192, r = idx - n * 192, c = r / 3, x = r - c * 3, gn = n0 + n;
        sm[NFVM + x * 8448 + c * NLDA + n] = (gn < NNODES) ? fv_g[gn * 192 + r] : 0.0f;
    }
    for (int idx = tid; idx < NTILE * 10; idx += 512) {
        int n = idx / 10, gn = n0 + n;
        sm[NATM + idx] = (gn < NNODES) ? attrs_g[gn * 10 + (idx - n * 10)] : 0.0f;
    }

    u64 acc_s[4][2], acc_v[3][4][2], Y[4][2];
#pragma unroll
    for (int rp = 0; rp < 4; rp++) { acc_s[rp][0] = 0ull; acc_s[rp][1] = 0ull; }
#pragma unroll
    for (int x = 0; x < 3; x++)
#pragma unroll
        for (int rp = 0; rp < 4; rp++) { acc_v[x][rp][0] = 0ull; acc_v[x][rp][1] = 0ull; }

    const float isc = rsqrtf(640.0f);

#pragma unroll 1
    for (int p = 0; p < 22; p++) {
        if (p == 21) asm volatile("cp.async.wait_group 0;" ::: "memory");
        else         asm volatile("cp.async.wait_group 1;" ::: "memory");
        __syncthreads();
        const float* WB = sm + ((p & 1) ? NWB1 : NWB0);

        if (p < 10) {
            gemm8x2<64, NLDA>(sm + NFSM + nb, WB + db, Y);
#pragma unroll
            for (int rp = 0; rp < 4; rp++) {
                u64 av2 = pack2(sm[NATM + (nb + 2*rp) * 10 + p],
                                sm[NATM + (nb + 2*rp + 1) * 10 + p]);
                acc_s[rp][0] = fma2(av2, Y[rp][0], acc_s[rp][0]);
                acc_s[rp][1] = fma2(av2, Y[rp][1], acc_s[rp][1]);
            }
        } else if (p < 20) {
            const int a = p - 10;
#pragma unroll 1
            for (int x = 0; x < 3; x++) {
                gemm8x2<64, NLDA>(sm + NFVM + x * 8448 + nb, WB + db, Y);
#pragma unroll
                for (int rp = 0; rp < 4; rp++) {
                    u64 av2 = pack2(sm[NATM + (nb + 2*rp) * 10 + a],
                                    sm[NATM + (nb + 2*rp + 1) * 10 + a]);
                    acc_v[x][rp][0] = fma2(av2, Y[rp][0], acc_v[x][rp][0]);
                    acc_v[x][rp][1] = fma2(av2, Y[rp][1], acc_v[x][rp][1]);
                }
            }
        } else if (p == 20) {
            gemm8x2<64, NLDA>(sm + NFSM + nb, WB + db, Y);
#pragma unroll
            for (int rp = 0; rp < 4; rp++) {
                float y0l, y0h, y1l, y1h;
                unpack2(Y[rp][0], y0l, y0h);
                unpack2(Y[rp][1], y1l, y1h);
                int gn0 = n0 + nb + 2*rp;
                if (gn0 < NNODES)
                    *(float2*)(g_s_scr + gn0 * 64 + db) = make_float2(y0l*0.125f, y1l*0.125f);
                if (gn0 + 1 < NNODES)
                    *(float2*)(g_s_scr + (gn0+1) * 64 + db) = make_float2(y0h*0.125f, y1h*0.125f);
            }
        } else {
#pragma unroll 1
            for (int x = 0; x < 3; x++) {
                gemm8x2<64, NLDA>(sm + NFVM + x * 8448 + nb, WB + db, Y);
#pragma unroll
                for (int rp = 0; rp < 4; rp++) {
                    float y0l, y0h, y1l, y1h;
                    unpack2(Y[rp][0], y0l, y0h);
                    unpack2(Y[rp][1], y1l, y1h);
                    int gn0 = n0 + nb + 2*rp;
                    if (gn0 < NNODES)
                        *(float2*)(g_v_scr + gn0 * 192 + x * 64 + db) =
                            make_float2(y0l*0.125f, y1l*0.125f);
                    if (gn0 + 1 < NNODES)
                        *(float2*)(g_v_scr + (gn0+1) * 192 + x * 64 + db) =
                            make_float2(y0h*0.125f, y1h*0.125f);
                }
            }
        }
        __syncthreads();
        if (p + 2 < 22) {
            float* dst = sm + ((p & 1) ? NWB1 : NWB0);
            int q = p + 2;
            const float* src = (q < 10) ? (Wscs + q * 64)
                             : (q < 20) ? (Wscv + (q - 10) * 64)
                             : (q == 20) ? Wses : Wsev;
            int ld = (q < 20) ? 640 : 64;
            stage_panel(dst, src, ld, tid);
        }
    }

#pragma unroll
    for (int rp = 0; rp < 4; rp++) {
        float s0l, s0h, s1l, s1h;
        unpack2(acc_s[rp][0], s0l, s0h);
        unpack2(acc_s[rp][1], s1l, s1h);
        float v0l[3], v0h[3], v1l[3], v1h[3];
#pragma unroll
        for (int x = 0; x < 3; x++) {
            unpack2(acc_v[x][rp][0], v0l[x], v0h[x]);
            unpack2(acc_v[x][rp][1], v1l[x], v1h[x]);
        }
        int gn0 = n0 + nb + 2*rp;
        if (gn0 < NNODES) {
            *(float2*)(out + SC_S_OFF + gn0 * 64 + db) = make_float2(s0l*isc, s1l*isc);
#pragma unroll
            for (int x = 0; x < 3; x++) {
                out[SC_V_OFF + (gn0 * 64 + db) * 3 + x]     = v0l[x] * isc;
                out[SC_V_OFF + (gn0 * 64 + db + 1) * 3 + x] = v1l[x] * isc;
            }
        }
        if (gn0 + 1 < NNODES) {
            *(float2*)(out + SC_S_OFF + (gn0+1) * 64 + db) = make_float2(s0h*isc, s1h*isc);
#pragma unroll
            for (int x = 0; x < 3; x++) {
                out[SC_V_OFF + ((gn0+1) * 64 + db) * 3 + x]     = v0h[x] * isc;
                out[SC_V_OFF + ((gn0+1) * 64 + db + 1) * 3 + x] = v1h[x] * isc;
            }
        }
    }
}

// ===================== K2: edge side — coalesced scatter/gather lanes ======
#define SA 0
#define SB 8960
#define SW1 17920
#define WS0 18432
#define WS1 22528
#define SMETA 26624
#define K2_SMEM_BYTES (27392 * 4)

__device__ __forceinline__ void store_actT(float* dst, const u64 Y[4][2],
                                           int nb, int db, float scale) {
#pragma unroll
    for (int c = 0; c < 2; c++) {
        float y0l, y0h, y1l, y1h, y2l, y2h, y3l, y3h;
        unpack2(Y[0][c], y0l, y0h);
        unpack2(Y[1][c], y1l, y1h);
        unpack2(Y[2][c], y2l, y2h);
        unpack2(Y[3][c], y3l, y3h);
        float* base = dst + (db + c) * 140 + nb;
        *(float4*)(base)     = make_float4(silu_f(y0l*scale), silu_f(y0h*scale),
                                           silu_f(y1l*scale), silu_f(y1h*scale));
        *(float4*)(base + 4) = make_float4(silu_f(y2l*scale), silu_f(y2h*scale),
                                           silu_f(y3l*scale), silu_f(y3h*scale));
    }
}

__device__ __forceinline__ void stage_w64(float* dst, const float* src,
                                          int ld_src, int col0, int tid) {
#pragma unroll
    for (int i = tid; i < 1024; i += 512) {
        int k = i >> 4, c4 = (i & 15) * 4;
        cp16(smaddr(dst + k * 64 + c4), src + k * ld_src + col0 + c4);
    }
    cp_commit();
}

__global__ void __launch_bounds__(512, 2) edge_kernel(
    const float* __restrict__ ef_g, const float* __restrict__ sh0_g,
    const float* __restrict__ sh1_g, const int* __restrict__ snd_g,
    const int* __restrict__ rcv_g,
    const float* __restrict__ W1, const float* __restrict__ W2,
    const float* __restrict__ W3, const float* __restrict__ W4) {
    extern __shared__ float sm[];
    const int tid = threadIdx.x;
    const int e0 = blockIdx.x * 128;
    const int tx = tid & 31, ty = tid >> 5;
    const int nb = ty * 8, db = tx * 2;
    // scatter lanes: 4 consecutive lanes = 1 edge; each covers a 4-ch sub-block
    // per instruction g the block moves by 16 channels -> contiguous 64B/edge.
    const int e_loc = tid >> 2, cg = tid & 3;
    const int chb = cg * 4;                    // 4-channel sub-block base
    const float i3 = rsqrtf(3.0f), i2 = rsqrtf(2.0f), is8 = rsqrtf(8.0f);
    u64 Y[4][2];

    if (tid < 128) {
        int ge = e0 + tid;
        ((int*)(sm + SMETA))[tid]       = snd_g[ge];
        ((int*)(sm + SMETA + 128))[tid] = rcv_g[ge];
        sm[SMETA + 256 + tid] = sh0_g[ge];
        sm[SMETA + 384 + tid] = sh1_g[ge * 3 + 0];
        sm[SMETA + 512 + tid] = sh1_g[ge * 3 + 1];
        sm[SMETA + 640 + tid] = sh1_g[ge * 3 + 2];
    }
    for (int i = tid; i < 1024; i += 512) {
        int e = i >> 3, k = i & 7;
        sm[SA + k * 140 + e] = ef_g[e0 * 8 + i];
    }
    sm[SW1 + tid] = W1[tid];
    stage_w64(sm + WS0, W2, 64, 0, tid);
    stage_w64(sm + WS1, W3, 64, 0, tid);
    __syncthreads();

    gemm8x2<8, 140>(sm + SA + nb, sm + SW1 + db, Y);
    store_actT(sm + SB, Y, nb, db, is8);
    asm volatile("cp.async.wait_group 1;" ::: "memory");
    __syncthreads();

    gemm8x2<64, 140>(sm + SB + nb, sm + WS0 + db, Y);
    store_actT(sm + SA, Y, nb, db, 0.125f);
    asm volatile("cp.async.wait_group 0;" ::: "memory");
    __syncthreads();
    stage_w64(sm + WS0, W4, 320, 0 * 64, tid);

    gemm8x2<64, 140>(sm + SA + nb, sm + WS1 + db, Y);
    store_actT(sm + SB, Y, nb, db, 0.125f);
    __syncthreads();
    stage_w64(sm + WS1, W4, 320, 1 * 64, tid);

    const int s = ((const int*)(sm + SMETA))[e_loc];
    const int r = ((const int*)(sm + SMETA + 128))[e_loc];
    const float sh0v = sm[SMETA + 256 + e_loc];
    const float qx = sm[SMETA + 384 + e_loc];
    const float qy = sm[SMETA + 512 + e_loc];
    const float qz = sm[SMETA + 640 + e_loc];
    const float* sep0 = g_s_scr + s * 64;
    const float* vp0  = g_v_scr + s * 192;
    const float* wrow0 = sm + SA + e_loc * 68;

#pragma unroll 1
    for (int p = 0; p < 5; p++) {
        float* buf = sm + ((p & 1) ? WS1 : WS0);
        if (p < 4) asm volatile("cp.async.wait_group 1;" ::: "memory");
        else       asm volatile("cp.async.wait_group 0;" ::: "memory");
        __syncthreads();

        gemm8x2<64, 140>(sm + SB + nb, buf + db, Y);
#pragma unroll
        for (int rp = 0; rp < 4; rp++) {
            float y0l, y0h, y1l, y1h;
            unpack2(Y[rp][0], y0l, y0h);
            unpack2(Y[rp][1], y1l, y1h);
            int rrow = nb + 2*rp;
            *(float2*)(sm + SA + rrow * 68 + db)       = make_float2(y0l*0.125f, y1l*0.125f);
            *(float2*)(sm + SA + (rrow + 1) * 68 + db) = make_float2(y0h*0.125f, y1h*0.125f);
        }
        __syncthreads();
        if (p + 2 <= 4) stage_w64(buf, W4, 320, (p + 2) * 64, tid);

        if (p == 0) {
            float* dst = g_ms + r * 128;
#pragma unroll
            for (int g = 0; g < 4; g++) {
                const int co = chb + g * 16;
                float4 wv = *(const float4*)(wrow0 + co);
                float4 se = *(const float4*)(sep0 + co);
                red4v(dst + co, f4muls(f4mul(wv, se), sh0v));
            }
        } else if (p == 1) {
            float* dst = g_ms + r * 128 + 64;
#pragma unroll
            for (int g = 0; g < 4; g++) {
                const int co = chb + g * 16;
                float4 wv = *(const float4*)(wrow0 + co);
                float4 vx = *(const float4*)(vp0 + co);
                float4 vy = *(const float4*)(vp0 + 64 + co);
                float4 vz = *(const float4*)(vp0 + 128 + co);
                float4 dt = f4add(f4add(f4muls(vx, qx), f4muls(vy, qy)), f4muls(vz, qz));
                red4v(dst + co, f4muls(f4mul(wv, dt), i3));
            }
        } else if (p == 2) {
            float* dst = g_mv + r * 576;
            float4 aqx = make_float4(qx,qx,qx,qx);
            float4 aqy = make_float4(qy,qy,qy,qy);
            float4 aqz = make_float4(qz,qz,qz,qz);
#pragma unroll
            for (int g = 0; g < 4; g++) {
                const int co = chb + g * 16;
                float4 wv = *(const float4*)(wrow0 + co);
                float4 se = *(const float4*)(sep0 + co);
                scatter_vec_group(dst + co * 3, f4mul(wv, se), aqx, aqy, aqz);
            }
        } else if (p == 3) {
            float* dst = g_mv + r * 576 + 192;
#pragma unroll
            for (int g = 0; g < 4; g++) {
                const int co = chb + g * 16;
                float4 wv = *(const float4*)(wrow0 + co);
                float4 vx = *(const float4*)(vp0 + co);
                float4 vy = *(const float4*)(vp0 + 64 + co);
                float4 vz = *(const float4*)(vp0 + 128 + co);
                scatter_vec_group(dst + co * 3, f4muls(wv, sh0v), vx, vy, vz);
            }
        } else {
            float* dst = g_mv + r * 576 + 384;
#pragma unroll
            for (int g = 0; g < 4; g++) {
                const int co = chb + g * 16;
                float4 wv = *(const float4*)(wrow0 + co);
                float4 vx = *(const float4*)(vp0 + co);
                float4 vy = *(const float4*)(vp0 + 64 + co);
                float4 vz = *(const float4*)(vp0 + 128 + co);
                float4 crx = f4sub(f4muls(vy, qz), f4muls(vz, qy));
                float4 cry = f4sub(f4muls(vz, qx), f4muls(vx, qz));
                float4 crz = f4sub(f4muls(vx, qy), f4muls(vy, qx));
                scatter_vec_group(dst + co * 3, f4muls(wv, i2), crx, cry, crz);
            }
        }
    }
}

// ===================== K3: output linear — R13 version =====================
#define K3_SMEM_BYTES (25344 * 4)
__global__ void __launch_bounds__(256, 2) out_kernel(
    const float* __restrict__ Wouts, const float* __restrict__ Woutv,
    float* __restrict__ out) {
    extern __shared__ float sm[];
    float* msm = sm;
    float* wbuf = sm + 13056;
    const int tid = threadIdx.x;
    const int n0 = blockIdx.x * 64;
    const int tx = tid & 31, ty = tid >> 5;
    const int nb = ty * 8, db = tx * 2;
    u64 Y[4][2];

    for (int idx = tid; idx < 8192; idx += 256) {
        int n = idx >> 7, k = idx & 127, gn = n0 + n;
        msm[k * 68 + n] = (gn < NNODES) ? g_ms[gn * 128 + k] : 0.0f;
    }
    for (int idx = tid; idx < 8192; idx += 256) wbuf[idx] = Wouts[idx];
    __syncthreads();
    gemm8x2<128, 68>(msm + nb, wbuf + db, Y);
    const float ss = rsqrtf(128.0f) / 16.0f;
#pragma unroll
    for (int rp = 0; rp < 4; rp++) {
        float y0l, y0h, y1l, y1h;
        unpack2(Y[rp][0], y0l, y0h);
        unpack2(Y[rp][1], y1l, y1h);
        int gn0 = n0 + nb + 2*rp;
        if (gn0 < NNODES)
            *(float2*)(out + gn0 * 64 + db) = make_float2(y0l*ss, y1l*ss);
        if (gn0 + 1 < NNODES)
            *(float2*)(out + (gn0+1) * 64 + db) = make_float2(y0h*ss, y1h*ss);
    }
    __syncthreads();
    for (int idx = tid; idx < 12288; idx += 256) wbuf[idx] = Woutv[idx];
    const float sv = rsqrtf(192.0f) / 16.0f;
#pragma unroll 1
    for (int x = 0; x < 3; x++) {
        __syncthreads();
        for (int idx = tid; idx < 12288; idx += 256) {
            int n = idx / 192, k = idx - n * 192, gn = n0 + n;
            msm[k * 68 + n] = (gn < NNODES) ? g_mv[gn * 576 + k * 3 + x] : 0.0f;
        }
        __syncthreads();
        gemm8x2<192, 68>(msm + nb, wbuf + db, Y);
#pragma unroll
        for (int rp = 0; rp < 4; rp++) {
            float y0l, y0h, y1l, y1h;
            unpack2(Y[rp][0], y0l, y0h);
            unpack2(Y[rp][1], y1l, y1h);
            int gn0 = n0 + nb + 2*rp;
            if (gn0 < NNODES) {
                out[OUT_V_OFF + gn0 * 192 + db * 3 + x]       = y0l * sv;
                out[OUT_V_OFF + gn0 * 192 + (db + 1) * 3 + x] = y1l * sv;
            }
            if (gn0 + 1 < NNODES) {
                out[OUT_V_OFF + (gn0+1) * 192 + db * 3 + x]       = y0h * sv;
                out[OUT_V_OFF + (gn0+1) * 192 + (db + 1) * 3 + x] = y1h * sv;
            }
        }
    }
}

// ===================== launch =====================
extern "C" void kernel_launch(void* const* d_in, const int* in_sizes, int n_in,
                              void* d_out, int out_size) {
    const float* attrs = (const float*)d_in[0];
    const float* fs    = (const float*)d_in[1];
    const float* fv    = (const float*)d_in[2];
    const float* sh0   = (const float*)d_in[3];
    const float* sh1   = (const float*)d_in[4];
    const float* ef    = (const float*)d_in[5];
    const int*   snd   = (const int*)d_in[6];
    const int*   rcv   = (const int*)d_in[7];
    const float* Wscs  = (const float*)d_in[8];
    const float* Wscv  = (const float*)d_in[9];
    const float* Wses  = (const float*)d_in[10];
    const float* Wsev  = (const float*)d_in[11];
    const float* W1    = (const float*)d_in[12];
    const float* W2    = (const float*)d_in[13];
    const float* W3    = (const float*)d_in[14];
    const float* W4    = (const float*)d_in[15];
    const float* Wouts = (const float*)d_in[16];
    const float* Woutv = (const float*)d_in[17];
    float* out = (float*)d_out;

    cudaFuncSetAttribute(node_kernel, cudaFuncAttributeMaxDynamicSharedMemorySize, K1_SMEM_BYTES);
    cudaFuncSetAttribute(edge_kernel, cudaFuncAttributeMaxDynamicSharedMemorySize, K2_SMEM_BYTES);
    cudaFuncSetAttribute(out_kernel,  cudaFuncAttributeMaxDynamicSharedMemorySize, K3_SMEM_BYTES);

    zero_kernel<<<1024, 256>>>();
    node_kernel<<<(NNODES + NTILE - 1) / NTILE, 512, K1_SMEM_BYTES>>>(
        attrs, fs, fv, Wscs, Wscv, Wses, Wsev, out);
    edge_kernel<<<NEDGES / 128, 512, K2_SMEM_BYTES>>>(
        ef, sh0, sh1, snd, rcv, W1, W2, W3, W4);
    out_kernel<<<(NNODES + 63) / 64, 256, K3_SMEM_BYTES>>>(Wouts, Woutv, out);
}

// round 17
// speedup vs baseline: 1.2554x; 1.1119x over previous
#include <cuda_runtime.h>

#define NNODES 50000
#define NEDGES 320000
#define OUT_V_OFF 3200000
#define SC_S_OFF  12800000
#define SC_V_OFF  16000000

typedef unsigned long long u64;

// ---- scratch (__device__ globals: allocation-free) ----
__device__ float g_s_scr[NNODES * 64];
__device__ float g_v_scr[NNODES * 192];   // [n][x][c]
__device__ float g_ms[NNODES * 128];      // [n][2C]
__device__ float g_mv[NNODES * 576];      // [n][3][3C]  (x-MAJOR: x*192 + path*64 + ch)

__device__ __forceinline__ float silu_f(float x) { return x / (1.0f + __expf(-x)); }

// ---- packed fp32x2 primitives ----
__device__ __forceinline__ u64 pack2(float lo, float hi) {
    u64 r; asm("mov.b64 %0, {%1, %2};" : "=l"(r) : "f"(lo), "f"(hi)); return r;
}
__device__ __forceinline__ u64 fma2(u64 a, u64 b, u64 c) {
    u64 d; asm("fma.rn.f32x2 %0, %1, %2, %3;" : "=l"(d) : "l"(a), "l"(b), "l"(c)); return d;
}
__device__ __forceinline__ void unpack2(u64 v, float& lo, float& hi) {
    asm("mov.b64 {%0, %1}, %2;" : "=f"(lo), "=f"(hi) : "l"(v));
}

__device__ __forceinline__ void red4v(float* p, float4 v) {
    asm volatile("red.global.add.v4.f32 [%0], {%1, %2, %3, %4};"
                 :: "l"(p), "f"(v.x), "f"(v.y), "f"(v.z), "f"(v.w) : "memory");
}

// ---- cp.async helpers ----
__device__ __forceinline__ unsigned smaddr(const void* p) {
    return (unsigned)__cvta_generic_to_shared(p);
}
__device__ __forceinline__ void cp16(unsigned dst, const void* src) {
    asm volatile("cp.async.cg.shared.global [%0], [%1], 16;" :: "r"(dst), "l"(src) : "memory");
}
__device__ __forceinline__ void cp_commit() {
    asm volatile("cp.async.commit_group;" ::: "memory");
}

__device__ __forceinline__ float4 f4mul(float4 a, float4 b) {
    return make_float4(a.x*b.x, a.y*b.y, a.z*b.z, a.w*b.w);
}
__device__ __forceinline__ float4 f4muls(float4 a, float s) {
    return make_float4(a.x*s, a.y*s, a.z*s, a.w*s);
}
__device__ __forceinline__ float4 f4sub(float4 a, float4 b) {
    return make_float4(a.x-b.x, a.y-b.y, a.z-b.z, a.w-b.w);
}
__device__ __forceinline__ float4 f4add(float4 a, float4 b) {
    return make_float4(a.x+b.x, a.y+b.y, a.z+b.z, a.w+b.w);
}

// 8x2 register-tile GEMM using packed fp32x2.
template <int K, int LDA>
__device__ __forceinline__ void gemm8x2(const float* __restrict__ A,
                                        const float* __restrict__ W,
                                        u64 Y[4][2]) {
#pragma unroll
    for (int rp = 0; rp < 4; rp++) { Y[rp][0] = 0ull; Y[rp][1] = 0ull; }
#pragma unroll 8
    for (int c = 0; c < K; c++) {
        ulonglong2 a01 = *(const ulonglong2*)(A + c * LDA);
        ulonglong2 a23 = *(const ulonglong2*)(A + c * LDA + 4);
        float2 w = *(const float2*)(W + c * 64);
        u64 w0 = pack2(w.x, w.x), w1 = pack2(w.y, w.y);
        Y[0][0] = fma2(a01.x, w0, Y[0][0]);
        Y[0][1] = fma2(a01.x, w1, Y[0][1]);
        Y[1][0] = fma2(a01.y, w0, Y[1][0]);
        Y[1][1] = fma2(a01.y, w1, Y[1][1]);
        Y[2][0] = fma2(a23.x, w0, Y[2][0]);
        Y[2][1] = fma2(a23.x, w1, Y[2][1]);
        Y[3][0] = fma2(a23.y, w0, Y[3][0]);
        Y[3][1] = fma2(a23.y, w1, Y[3][1]);
    }
}

// ===================== K0: zero scratch =====================
__global__ void zero_kernel() {
    long i = (long)blockIdx.x * blockDim.x + threadIdx.x;
    long t = (long)gridDim.x * blockDim.x;
    float4 z = make_float4(0.f, 0.f, 0.f, 0.f);
    for (long j = i; j < (long)NNODES * 128 / 4; j += t) ((float4*)g_ms)[j] = z;
    for (long j = i; j < (long)NNODES * 576 / 4; j += t) ((float4*)g_mv)[j] = z;
}

// ===================== K1: node side — 64-node tiles, 2 CTAs/SM ====
// 256 threads, grid 782. smem (floats):
//   fsm @0     : [64][68] = 4352
//   fvm @4352  : 3 x [64][68] = 13056
//   WB0 @17408 : 4096
//   WB1 @21504 : 4096
//   atm @25600 : [64][10] = 640
// total 26240 floats = 105 KB -> 2 CTAs/SM (16 warps, decoupled barriers)
#define NLDA 68
#define NFSM 0
#define NFVM 4352
#define NWB0 17408
#define NWB1 21504
#define NATM 25600
#define K1_SMEM_BYTES (26240 * 4)
#define NTILE 64

__device__ __forceinline__ void stage_panel(float* dst, const float* src,
                                            int ld_src, int tid) {
#pragma unroll
    for (int i = tid; i < 1024; i += 256) {
        int k = i >> 4, c4 = (i & 15) * 4;
        cp16(smaddr(dst + k * 64 + c4), src + k * ld_src + c4);
    }
    cp_commit();
}

__global__ void __launch_bounds__(256, 2) node_kernel(
    const float* __restrict__ attrs_g, const float* __restrict__ fs_g,
    const float* __restrict__ fv_g,
    const float* __restrict__ Wscs, const float* __restrict__ Wscv,
    const float* __restrict__ Wses, const float* __restrict__ Wsev,
    float* __restrict__ out) {
    extern __shared__ float sm[];
    const int tid = threadIdx.x;
    const int n0 = blockIdx.x * NTILE;
    const int tx = tid & 31, ty = tid >> 5;   // ty 0..7 (8-row grp), tx 0..31 (2-col)
    const int nb = ty * 8, db = tx * 2;

    stage_panel(sm + NWB0, Wscs + 0 * 64, 640, tid);
    stage_panel(sm + NWB1, Wscs + 1 * 64, 640, tid);

    for (int idx = tid; idx < NTILE * 64; idx += 256) {
        int n = idx >> 6, c = idx & 63, gn = n0 + n;
        sm[NFSM + c * NLDA + n] = (gn < NNODES) ? fs_g[gn * 64 + c] : 0.0f;
    }
    for (int idx = tid; idx < NTILE * 192; idx += 256) {
        int n = idx / 192, r = idx - n * 192, c = r / 3, x = r - c * 3, gn = n0 + n;
        sm[NFVM + x * 4352 + c * NLDA + n] = (gn < NNODES) ? fv_g[gn * 192 + r] : 0.0f;
    }
    for (int idx = tid; idx < NTILE * 10; idx += 256) {
        int n = idx / 10, gn = n0 + n;
        sm[NATM + idx] = (gn < NNODES) ? attrs_g[gn * 10 + (idx - n * 10)] : 0.0f;
    }

    u64 acc_s[4][2], acc_v[3][4][2], Y[4][2];
#pragma unroll
    for (int rp = 0; rp < 4; rp++) { acc_s[rp][0] = 0ull; acc_s[rp][1] = 0ull; }
#pragma unroll
    for (int x = 0; x < 3; x++)
#pragma unroll
        for (int rp = 0; rp < 4; rp++) { acc_v[x][rp][0] = 0ull; acc_v[x][rp][1] = 0ull; }

    const float isc = rsqrtf(640.0f);

#pragma unroll 1
    for (int p = 0; p < 22; p++) {
        if (p == 21) asm volatile("cp.async.wait_group 0;" ::: "memory");
        else         asm volatile("cp.async.wait_group 1;" ::: "memory");
        __syncthreads();
        const float* WB = sm + ((p & 1) ? NWB1 : NWB0);

        if (p < 10) {
            gemm8x2<64, NLDA>(sm + NFSM + nb, WB + db, Y);
#pragma unroll
            for (int rp = 0; rp < 4; rp++) {
                u64 av2 = pack2(sm[NATM + (nb + 2*rp) * 10 + p],
                                sm[NATM + (nb + 2*rp + 1) * 10 + p]);
                acc_s[rp][0] = fma2(av2, Y[rp][0], acc_s[rp][0]);
                acc_s[rp][1] = fma2(av2, Y[rp][1], acc_s[rp][1]);
            }
        } else if (p < 20) {
            const int a = p - 10;
#pragma unroll 1
            for (int x = 0; x < 3; x++) {
                gemm8x2<64, NLDA>(sm + NFVM + x * 4352 + nb, WB + db, Y);
#pragma unroll
                for (int rp = 0; rp < 4; rp++) {
                    u64 av2 = pack2(sm[NATM + (nb + 2*rp) * 10 + a],
                                    sm[NATM + (nb + 2*rp + 1) * 10 + a]);
                    acc_v[x][rp][0] = fma2(av2, Y[rp][0], acc_v[x][rp][0]);
                    acc_v[x][rp][1] = fma2(av2, Y[rp][1], acc_v[x][rp][1]);
                }
            }
        } else if (p == 20) {
            gemm8x2<64, NLDA>(sm + NFSM + nb, WB + db, Y);
#pragma unroll
            for (int rp = 0; rp < 4; rp++) {
                float y0l, y0h, y1l, y1h;
                unpack2(Y[rp][0], y0l, y0h);
                unpack2(Y[rp][1], y1l, y1h);
                int gn0 = n0 + nb + 2*rp;
                if (gn0 < NNODES)
                    *(float2*)(g_s_scr + gn0 * 64 + db) = make_float2(y0l*0.125f, y1l*0.125f);
                if (gn0 + 1 < NNODES)
                    *(float2*)(g_s_scr + (gn0+1) * 64 + db) = make_float2(y0h*0.125f, y1h*0.125f);
            }
        } else {
#pragma unroll 1
            for (int x = 0; x < 3; x++) {
                gemm8x2<64, NLDA>(sm + NFVM + x * 4352 + nb, WB + db, Y);
#pragma unroll
                for (int rp = 0; rp < 4; rp++) {
                    float y0l, y0h, y1l, y1h;
                    unpack2(Y[rp][0], y0l, y0h);
                    unpack2(Y[rp][1], y1l, y1h);
                    int gn0 = n0 + nb + 2*rp;
                    if (gn0 < NNODES)
                        *(float2*)(g_v_scr + gn0 * 192 + x * 64 + db) =
                            make_float2(y0l*0.125f, y1l*0.125f);
                    if (gn0 + 1 < NNODES)
                        *(float2*)(g_v_scr + (gn0+1) * 192 + x * 64 + db) =
                            make_float2(y0h*0.125f, y1h*0.125f);
                }
            }
        }
        __syncthreads();
        if (p + 2 < 22) {
            float* dst = sm + ((p & 1) ? NWB1 : NWB0);
            int q = p + 2;
            const float* src = (q < 10) ? (Wscs + q * 64)
                             : (q < 20) ? (Wscv + (q - 10) * 64)
                             : (q == 20) ? Wses : Wsev;
            int ld = (q < 20) ? 640 : 64;
            stage_panel(dst, src, ld, tid);
        }
    }

#pragma unroll
    for (int rp = 0; rp < 4; rp++) {
        float s0l, s0h, s1l, s1h;
        unpack2(acc_s[rp][0], s0l, s0h);
        unpack2(acc_s[rp][1], s1l, s1h);
        float v0l[3], v0h[3], v1l[3], v1h[3];
#pragma unroll
        for (int x = 0; x < 3; x++) {
            unpack2(acc_v[x][rp][0], v0l[x], v0h[x]);
            unpack2(acc_v[x][rp][1], v1l[x], v1h[x]);
        }
        int gn0 = n0 + nb + 2*rp;
        if (gn0 < NNODES) {
            *(float2*)(out + SC_S_OFF + gn0 * 64 + db) = make_float2(s0l*isc, s1l*isc);
#pragma unroll
            for (int x = 0; x < 3; x++) {
                out[SC_V_OFF + (gn0 * 64 + db) * 3 + x]     = v0l[x] * isc;
                out[SC_V_OFF + (gn0 * 64 + db + 1) * 3 + x] = v1l[x] * isc;
            }
        }
        if (gn0 + 1 < NNODES) {
            *(float2*)(out + SC_S_OFF + (gn0+1) * 64 + db) = make_float2(s0h*isc, s1h*isc);
#pragma unroll
            for (int x = 0; x < 3; x++) {
                out[SC_V_OFF + ((gn0+1) * 64 + db) * 3 + x]     = v0h[x] * isc;
                out[SC_V_OFF + ((gn0+1) * 64 + db + 1) * 3 + x] = v1h[x] * isc;
            }
        }
    }
}

// ===================== K2: edge side — x-major g_mv scatter ======
#define SA 0
#define SB 8960
#define SW1 17920
#define WS0 18432
#define WS1 22528
#define SMETA 26624
#define K2_SMEM_BYTES (27392 * 4)

__device__ __forceinline__ void store_actT(float* dst, const u64 Y[4][2],
                                           int nb, int db, float scale) {
#pragma unroll
    for (int c = 0; c < 2; c++) {
        float y0l, y0h, y1l, y1h, y2l, y2h, y3l, y3h;
        unpack2(Y[0][c], y0l, y0h);
        unpack2(Y[1][c], y1l, y1h);
        unpack2(Y[2][c], y2l, y2h);
        unpack2(Y[3][c], y3l, y3h);
        float* base = dst + (db + c) * 140 + nb;
        *(float4*)(base)     = make_float4(silu_f(y0l*scale), silu_f(y0h*scale),
                                           silu_f(y1l*scale), silu_f(y1h*scale));
        *(float4*)(base + 4) = make_float4(silu_f(y2l*scale), silu_f(y2h*scale),
                                           silu_f(y3l*scale), silu_f(y3h*scale));
    }
}

__device__ __forceinline__ void stage_w64(float* dst, const float* src,
                                          int ld_src, int col0, int tid) {
#pragma unroll
    for (int i = tid; i < 1024; i += 512) {
        int k = i >> 4, c4 = (i & 15) * 4;
        cp16(smaddr(dst + k * 64 + c4), src + k * ld_src + col0 + c4);
    }
    cp_commit();
}

__global__ void __launch_bounds__(512, 2) edge_kernel(
    const float* __restrict__ ef_g, const float* __restrict__ sh0_g,
    const float* __restrict__ sh1_g, const int* __restrict__ snd_g,
    const int* __restrict__ rcv_g,
    const float* __restrict__ W1, const float* __restrict__ W2,
    const float* __restrict__ W3, const float* __restrict__ W4) {
    extern __shared__ float sm[];
    const int tid = threadIdx.x;
    const int e0 = blockIdx.x * 128;
    const int tx = tid & 31, ty = tid >> 5;
    const int nb = ty * 8, db = tx * 2;
    const int e_loc = tid >> 2, cg = tid & 3;
    const int chb = cg * 4;
    const float i3 = rsqrtf(3.0f), i2 = rsqrtf(2.0f), is8 = rsqrtf(8.0f);
    u64 Y[4][2];

    if (tid < 128) {
        int ge = e0 + tid;
        ((int*)(sm + SMETA))[tid]       = snd_g[ge];
        ((int*)(sm + SMETA + 128))[tid] = rcv_g[ge];
        sm[SMETA + 256 + tid] = sh0_g[ge];
        sm[SMETA + 384 + tid] = sh1_g[ge * 3 + 0];
        sm[SMETA + 512 + tid] = sh1_g[ge * 3 + 1];
        sm[SMETA + 640 + tid] = sh1_g[ge * 3 + 2];
    }
    for (int i = tid; i < 1024; i += 512) {
        int e = i >> 3, k = i & 7;
        sm[SA + k * 140 + e] = ef_g[e0 * 8 + i];
    }
    sm[SW1 + tid] = W1[tid];
    stage_w64(sm + WS0, W2, 64, 0, tid);
    stage_w64(sm + WS1, W3, 64, 0, tid);
    __syncthreads();

    gemm8x2<8, 140>(sm + SA + nb, sm + SW1 + db, Y);
    store_actT(sm + SB, Y, nb, db, is8);
    asm volatile("cp.async.wait_group 1;" ::: "memory");
    __syncthreads();

    gemm8x2<64, 140>(sm + SB + nb, sm + WS0 + db, Y);
    store_actT(sm + SA, Y, nb, db, 0.125f);
    asm volatile("cp.async.wait_group 0;" ::: "memory");
    __syncthreads();
    stage_w64(sm + WS0, W4, 320, 0 * 64, tid);

    gemm8x2<64, 140>(sm + SA + nb, sm + WS1 + db, Y);
    store_actT(sm + SB, Y, nb, db, 0.125f);
    __syncthreads();
    stage_w64(sm + WS1, W4, 320, 1 * 64, tid);

    const int s = ((const int*)(sm + SMETA))[e_loc];
    const int r = ((const int*)(sm + SMETA + 128))[e_loc];
    const float sh0v = sm[SMETA + 256 + e_loc];
    const float qx = sm[SMETA + 384 + e_loc];
    const float qy = sm[SMETA + 512 + e_loc];
    const float qz = sm[SMETA + 640 + e_loc];
    const float* sep0 = g_s_scr + s * 64;
    const float* vp0  = g_v_scr + s * 192;
    const float* wrow0 = sm + SA + e_loc * 68;

#pragma unroll 1
    for (int p = 0; p < 5; p++) {
        float* buf = sm + ((p & 1) ? WS1 : WS0);
        if (p < 4) asm volatile("cp.async.wait_group 1;" ::: "memory");
        else       asm volatile("cp.async.wait_group 0;" ::: "memory");
        __syncthreads();

        gemm8x2<64, 140>(sm + SB + nb, buf + db, Y);
#pragma unroll
        for (int rp = 0; rp < 4; rp++) {
            float y0l, y0h, y1l, y1h;
            unpack2(Y[rp][0], y0l, y0h);
            unpack2(Y[rp][1], y1l, y1h);
            int rrow = nb + 2*rp;
            *(float2*)(sm + SA + rrow * 68 + db)       = make_float2(y0l*0.125f, y1l*0.125f);
            *(float2*)(sm + SA + (rrow + 1) * 68 + db) = make_float2(y0h*0.125f, y1h*0.125f);
        }
        __syncthreads();
        if (p + 2 <= 4) stage_w64(buf, W4, 320, (p + 2) * 64, tid);

        if (p == 0) {
            float* dst = g_ms + r * 128;
#pragma unroll
            for (int g = 0; g < 4; g++) {
                const int co = chb + g * 16;
                float4 wv = *(const float4*)(wrow0 + co);
                float4 se = *(const float4*)(sep0 + co);
                red4v(dst + co, f4muls(f4mul(wv, se), sh0v));
            }
        } else if (p == 1) {
            float* dst = g_ms + r * 128 + 64;
#pragma unroll
            for (int g = 0; g < 4; g++) {
                const int co = chb + g * 16;
                float4 wv = *(const float4*)(wrow0 + co);
                float4 vx = *(const float4*)(vp0 + co);
                float4 vy = *(const float4*)(vp0 + 64 + co);
                float4 vz = *(const float4*)(vp0 + 128 + co);
                float4 dt = f4add(f4add(f4muls(vx, qx), f4muls(vy, qy)), f4muls(vz, qz));
                red4v(dst + co, f4muls(f4mul(wv, dt), i3));
            }
        } else if (p == 2) {
            // g_mv x-major: n*576 + x*192 + 0 + co
            float* dst = g_mv + r * 576;
#pragma unroll
            for (int g = 0; g < 4; g++) {
                const int co = chb + g * 16;
                float4 wv = *(const float4*)(wrow0 + co);
                float4 se = *(const float4*)(sep0 + co);
                float4 ws = f4mul(wv, se);
                red4v(dst + 0 * 192 + co, f4muls(ws, qx));
                red4v(dst + 1 * 192 + co, f4muls(ws, qy));
                red4v(dst + 2 * 192 + co, f4muls(ws, qz));
            }
        } else if (p == 3) {
            float* dst = g_mv + r * 576 + 64;
#pragma unroll
            for (int g = 0; g < 4; g++) {
                const int co = chb + g * 16;
                float4 wv = *(const float4*)(wrow0 + co);
                float4 vx = *(const float4*)(vp0 + co);
                float4 vy = *(const float4*)(vp0 + 64 + co);
                float4 vz = *(const float4*)(vp0 + 128 + co);
                float4 wss = f4muls(wv, sh0v);
                red4v(dst + 0 * 192 + co, f4mul(wss, vx));
                red4v(dst + 1 * 192 + co, f4mul(wss, vy));
                red4v(dst + 2 * 192 + co, f4mul(wss, vz));
            }
        } else {
            float* dst = g_mv + r * 576 + 128;
#pragma unroll
            for (int g = 0; g < 4; g++) {
                const int co = chb + g * 16;
                float4 wv = *(const float4*)(wrow0 + co);
                float4 vx = *(const float4*)(vp0 + co);
                float4 vy = *(const float4*)(vp0 + 64 + co);
                float4 vz = *(const float4*)(vp0 + 128 + co);
                float4 wvi = f4muls(wv, i2);
                float4 crx = f4sub(f4muls(vy, qz), f4muls(vz, qy));
                float4 cry = f4sub(f4muls(vz, qx), f4muls(vx, qz));
                float4 crz = f4sub(f4muls(vx, qy), f4muls(vy, qx));
                red4v(dst + 0 * 192 + co, f4mul(wvi, crx));
                red4v(dst + 1 * 192 + co, f4mul(wvi, cry));
                red4v(dst + 2 * 192 + co, f4mul(wvi, crz));
            }
        }
    }
}

// ===================== K3: output linear — coalesced g_mv staging ==========
#define K3_SMEM_BYTES (25344 * 4)
__global__ void __launch_bounds__(256, 2) out_kernel(
    const float* __restrict__ Wouts, const float* __restrict__ Woutv,
    float* __restrict__ out) {
    extern __shared__ float sm[];
    float* msm = sm;
    float* wbuf = sm + 13056;
    const int tid = threadIdx.x;
    const int n0 = blockIdx.x * 64;
    const int tx = tid & 31, ty = tid >> 5;
    const int nb = ty * 8, db = tx * 2;
    u64 Y[4][2];

    for (int idx = tid; idx < 8192; idx += 256) {
        int n = idx >> 7, k = idx & 127, gn = n0 + n;
        msm[k * 68 + n] = (gn < NNODES) ? g_ms[gn * 128 + k] : 0.0f;
    }
    for (int idx = tid; idx < 8192; idx += 256) wbuf[idx] = Wouts[idx];
    __syncthreads();
    gemm8x2<128, 68>(msm + nb, wbuf + db, Y);
    const float ss = rsqrtf(128.0f) / 16.0f;
#pragma unroll
    for (int rp = 0; rp < 4; rp++) {
        float y0l, y0h, y1l, y1h;
        unpack2(Y[rp][0], y0l, y0h);
        unpack2(Y[rp][1], y1l, y1h);
        int gn0 = n0 + nb + 2*rp;
        if (gn0 < NNODES)
            *(float2*)(out + gn0 * 64 + db) = make_float2(y0l*ss, y1l*ss);
        if (gn0 + 1 < NNODES)
            *(float2*)(out + (gn0+1) * 64 + db) = make_float2(y0h*ss, y1h*ss);
    }
    __syncthreads();
    for (int idx = tid; idx < 12288; idx += 256) wbuf[idx] = Woutv[idx];
    const float sv = rsqrtf(192.0f) / 16.0f;
#pragma unroll 1
    for (int x = 0; x < 3; x++) {
        __syncthreads();
        // g_mv x-major: fully k-contiguous (coalesced) staging reads
        for (int idx = tid; idx < 12288; idx += 256) {
            int n = idx / 192, k = idx - n * 192, gn = n0 + n;
            msm[k * 68 + n] = (gn < NNODES) ? g_mv[gn * 576 + x * 192 + k] : 0.0f;
        }
        __syncthreads();
        gemm8x2<192, 68>(msm + nb, wbuf + db, Y);
#pragma unroll
        for (int rp = 0; rp < 4; rp++) {
            float y0l, y0h, y1l, y1h;
            unpack2(Y[rp][0], y0l, y0h);
            unpack2(Y[rp][1], y1l, y1h);
            int gn0 = n0 + nb + 2*rp;
            if (gn0 < NNODES) {
                out[OUT_V_OFF + gn0 * 192 + db * 3 + x]       = y0l * sv;
                out[OUT_V_OFF + gn0 * 192 + (db + 1) * 3 + x] = y1l * sv;
            }
            if (gn0 + 1 < NNODES) {
                out[OUT_V_OFF + (gn0+1) * 192 + db * 3 + x]       = y0h * sv;
                out[OUT_V_OFF + (gn0+1) * 192 + (db + 1) * 3 + x] = y1h * sv;
            }
        }
    }
}

// ===================== launch =====================
extern "C" void kernel_launch(void* const* d_in, const int* in_sizes, int n_in,
                              void* d_out, int out_size) {
    const float* attrs = (const float*)d_in[0];
    const float* fs    = (const float*)d_in[1];
    const float* fv    = (const float*)d_in[2];
    const float* sh0   = (const float*)d_in[3];
    const float* sh1   = (const float*)d_in[4];
    const float* ef    = (const float*)d_in[5];
    const int*   snd   = (const int*)d_in[6];
    const int*   rcv   = (const int*)d_in[7];
    const float* Wscs  = (const float*)d_in[8];
    const float* Wscv  = (const float*)d_in[9];
    const float* Wses  = (const float*)d_in[10];
    const float* Wsev  = (const float*)d_in[11];
    const float* W1    = (const float*)d_in[12];
    const float* W2    = (const float*)d_in[13];
    const float* W3    = (const float*)d_in[14];
    const float* W4    = (const float*)d_in[15];
    const float* Wouts = (const float*)d_in[16];
    const float* Woutv = (const float*)d_in[17];
    float* out = (float*)d_out;

    cudaFuncSetAttribute(node_kernel, cudaFuncAttributeMaxDynamicSharedMemorySize, K1_SMEM_BYTES);
    cudaFuncSetAttribute(edge_kernel, cudaFuncAttributeMaxDynamicSharedMemorySize, K2_SMEM_BYTES);
    cudaFuncSetAttribute(out_kernel,  cudaFuncAttributeMaxDynamicSharedMemorySize, K3_SMEM_BYTES);

    zero_kernel<<<1024, 256>>>();
    node_kernel<<<(NNODES + NTILE - 1) / NTILE, 256, K1_SMEM_BYTES>>>(
        attrs, fs, fv, Wscs, Wscv, Wses, Wsev, out);
    edge_kernel<<<NEDGES / 128, 512, K2_SMEM_BYTES>>>(
        ef, sh0, sh1, snd, rcv, W1, W2, W3, W4);
    out_kernel<<<(NNODES + 63) / 64, 256, K3_SMEM_BYTES>>>(Wouts, Woutv, out);
}